// round 12
// baseline (speedup 1.0000x reference)
#include <cuda_runtime.h>
#include <cuda_fp16.h>
#include <cuda_bf16.h>
#include <cstdint>

// Problem constants: N_NODES=50000, N_EDGES=640000, D=128, OUT=1
#define MAX_NODES 50000
#define D 128
#define TABLE_BYTES (MAX_NODES * 4)     // 200000 B of __half2
#define FILL_CHUNK 50000                // 4 bulk chunks (16B-multiple)
#define SMEM_TOTAL (TABLE_BYTES + 16 + 2 * D * 4)  // table + mbar + W1 + W2

// Packed per-node projections: lo = dot(X[n],W1), hi = dot(X[n],W2), fp16.
__device__ __align__(16) __half2 d_pack[MAX_NODES];
// Monotonic arrival counter; generation trick makes graph replays deterministic.
__device__ unsigned long long d_ctr;

__device__ __forceinline__ float dot4(float4 a, float4 b) {
    return a.x * b.x + a.y * b.y + a.z * b.z + a.w * b.w;
}

#define CLAMP(v) min(max((v), 0), MAX_NODES - 1)

// Fused persistent kernel: one block per SM.
// Phase A: compute this block's node slice -> d_pack (global).
// Then: prefetch edge indices; grid-wide arrive+spin; bulk-fill smem table;
// mbarrier wait; smem gathers; store.
__global__ void __launch_bounds__(1024, 1)
fused_kernel(const float* __restrict__ X,
             const int* __restrict__ ei,
             const float* __restrict__ W1,
             const float* __restrict__ W2,
             float* __restrict__ out,
             int n_nodes, int n_edges) {
    extern __shared__ __align__(16) unsigned char smem_raw[];
    __half2* s_p = reinterpret_cast<__half2*>(smem_raw);
    float* sW1 = reinterpret_cast<float*>(smem_raw + TABLE_BYTES + 16);
    float* sW2 = sW1 + D;

    uint32_t smem_base;
    asm("{ .reg .u64 t; cvta.to.shared.u64 t, %1; cvt.u32.u64 %0, t; }"
        : "=r"(smem_base) : "l"(smem_raw));
    uint32_t mbar = smem_base + TABLE_BYTES;

    int tid = threadIdx.x;
    int G = gridDim.x;

    if (tid == 0) {
        asm volatile("mbarrier.init.shared.b64 [%0], 1;" :: "r"(mbar) : "memory");
    }
    if (tid < D) {
        sW1[tid] = W1[tid];
        sW2[tid] = W2[tid];
    }
    __syncthreads();

    // ---- Phase A: project this block's node slice ----
    int npb = (n_nodes + G - 1) / G;
    int nstart = blockIdx.x * npb;
    int nend = min(nstart + npb, n_nodes);

    int lane = tid & 31;
    int sub  = lane & 7;
    int grp  = lane >> 3;
    int wid  = tid >> 5;            // 0..31

    const float4* Xv = reinterpret_cast<const float4*>(X);
    const float4* w1 = reinterpret_cast<const float4*>(sW1);
    const float4* w2 = reinterpret_cast<const float4*>(sW2);
    float4 w1_0 = w1[sub], w1_1 = w1[sub + 8], w1_2 = w1[sub + 16], w1_3 = w1[sub + 24];
    float4 w2_0 = w2[sub], w2_1 = w2[sub + 8], w2_2 = w2[sub + 16], w2_3 = w2[sub + 24];

    for (int base = nstart; base < nend; base += 256) {
        int n0 = base + wid * 8;
        int rowA = n0 + grp;
        int rowB = n0 + 4 + grp;

        float sA1 = 0.f, sA2 = 0.f, sB1 = 0.f, sB2 = 0.f;
        if (rowA < nend) {
            float4 a0 = Xv[(size_t)rowA * 32 + sub + 0];
            float4 a1 = Xv[(size_t)rowA * 32 + sub + 8];
            float4 a2 = Xv[(size_t)rowA * 32 + sub + 16];
            float4 a3 = Xv[(size_t)rowA * 32 + sub + 24];
            sA1 = dot4(a0, w1_0) + dot4(a1, w1_1) + dot4(a2, w1_2) + dot4(a3, w1_3);
            sA2 = dot4(a0, w2_0) + dot4(a1, w2_1) + dot4(a2, w2_2) + dot4(a3, w2_3);
        }
        if (rowB < nend) {
            float4 b0 = Xv[(size_t)rowB * 32 + sub + 0];
            float4 b1 = Xv[(size_t)rowB * 32 + sub + 8];
            float4 b2 = Xv[(size_t)rowB * 32 + sub + 16];
            float4 b3 = Xv[(size_t)rowB * 32 + sub + 24];
            sB1 = dot4(b0, w1_0) + dot4(b1, w1_1) + dot4(b2, w1_2) + dot4(b3, w1_3);
            sB2 = dot4(b0, w2_0) + dot4(b1, w2_1) + dot4(b2, w2_2) + dot4(b3, w2_3);
        }

        #pragma unroll
        for (int off = 4; off > 0; off >>= 1) {
            sA1 += __shfl_xor_sync(0xFFFFFFFF, sA1, off);
            sA2 += __shfl_xor_sync(0xFFFFFFFF, sA2, off);
            sB1 += __shfl_xor_sync(0xFFFFFFFF, sB1, off);
            sB2 += __shfl_xor_sync(0xFFFFFFFF, sB2, off);
        }

        if (sub == 0) {
            if (rowA < nend) d_pack[rowA] = __floats2half2_rn(sA1, sA2);
            if (rowB < nend) d_pack[rowB] = __floats2half2_rn(sB1, sB2);
        }
    }
    __syncthreads();   // block's phase A fully done

    // ---- Signal arrival (tid 0), then everyone prefetches indices ----
    unsigned long long target = 0;
    if (tid == 0) {
        __threadfence();   // d_pack writes visible device-wide
        unsigned long long old = atomicAdd(&d_ctr, 1ULL);
        target = (old / G + 1) * (unsigned long long)G;
    }

    // Prefetch ALL of this thread's edge indices (overlaps other blocks' phase A).
    int total_quads = n_edges >> 2;
    int qpb = (total_quads + G - 1) / G;
    int q_start = blockIdx.x * qpb;
    int q_end = min(q_start + qpb, total_quads);

    int q0 = q_start + tid;
    int q1 = q0 + 1024;
    bool v0 = q0 < q_end;
    bool v1 = q1 < q_end;
    int4 s4a = make_int4(0,0,0,0), d4a = s4a, s4b = s4a, d4b = s4a;
    if (v0) {
        s4a = *reinterpret_cast<const int4*>(ei + q0 * 4);
        d4a = *reinterpret_cast<const int4*>(ei + n_edges + q0 * 4);
    }
    if (v1) {
        s4b = *reinterpret_cast<const int4*>(ei + q1 * 4);
        d4b = *reinterpret_cast<const int4*>(ei + n_edges + q1 * 4);
    }

    // ---- tid 0: spin until all blocks arrived, then issue bulk fill ----
    if (tid == 0) {
        unsigned long long cur;
        do {
            asm volatile("ld.acquire.gpu.u64 %0, [%1];"
                         : "=l"(cur) : "l"(&d_ctr) : "memory");
        } while (cur < target);
        asm volatile("fence.proxy.async;" ::: "memory");

        asm volatile("mbarrier.arrive.expect_tx.shared.b64 _, [%0], %1;"
                     :: "r"(mbar), "r"((uint32_t)TABLE_BYTES) : "memory");
        const char* src = reinterpret_cast<const char*>(d_pack);
        #pragma unroll
        for (int c = 0; c < 4; c++) {
            asm volatile(
                "cp.async.bulk.shared::cta.global.mbarrier::complete_tx::bytes "
                "[%0], [%1], %2, [%3];"
                :: "r"(smem_base + c * FILL_CHUNK), "l"(src + (size_t)c * FILL_CHUNK),
                   "r"((uint32_t)FILL_CHUNK), "r"(mbar) : "memory");
        }
    }

    // ---- Everyone: wait for the table ----
    {
        uint32_t done;
        asm volatile(
            "{\n\t"
            ".reg .pred p;\n\t"
            "mbarrier.try_wait.parity.acquire.cta.shared::cta.b64 p, [%1], 0;\n\t"
            "selp.b32 %0, 1, 0, p;\n\t"
            "}"
            : "=r"(done) : "r"(mbar) : "memory");
        if (!done) {
            asm volatile(
                "{\n\t"
                ".reg .pred P1;\n\t"
                "WL_%=:\n\t"
                "mbarrier.try_wait.parity.acquire.cta.shared::cta.b64 P1, [%0], 0, 0x989680;\n\t"
                "@P1 bra.uni WD_%=;\n\t"
                "bra.uni WL_%=;\n\t"
                "WD_%=:\n\t"
                "}"
                :: "r"(mbar) : "memory");
        }
    }

    // ---- Gather + store ----
    if (v0) {
        float4 r;
        r.x = __low2float(s_p[CLAMP(s4a.x)]) + __high2float(s_p[CLAMP(d4a.x)]);
        r.y = __low2float(s_p[CLAMP(s4a.y)]) + __high2float(s_p[CLAMP(d4a.y)]);
        r.z = __low2float(s_p[CLAMP(s4a.z)]) + __high2float(s_p[CLAMP(d4a.z)]);
        r.w = __low2float(s_p[CLAMP(s4a.w)]) + __high2float(s_p[CLAMP(d4a.w)]);
        *reinterpret_cast<float4*>(out + q0 * 4) = r;
    }
    if (v1) {
        float4 r;
        r.x = __low2float(s_p[CLAMP(s4b.x)]) + __high2float(s_p[CLAMP(d4b.x)]);
        r.y = __low2float(s_p[CLAMP(s4b.y)]) + __high2float(s_p[CLAMP(d4b.y)]);
        r.z = __low2float(s_p[CLAMP(s4b.z)]) + __high2float(s_p[CLAMP(d4b.z)]);
        r.w = __low2float(s_p[CLAMP(s4b.w)]) + __high2float(s_p[CLAMP(d4b.w)]);
        *reinterpret_cast<float4*>(out + q1 * 4) = r;
    }
    // Generic leftover (if qpb > 2048) and scalar tail — rare paths.
    for (int q = q_start + 2 * 1024 + tid; q < q_end; q += 1024) {
        int4 s4 = *reinterpret_cast<const int4*>(ei + q * 4);
        int4 d4 = *reinterpret_cast<const int4*>(ei + n_edges + q * 4);
        float4 r;
        r.x = __low2float(s_p[CLAMP(s4.x)]) + __high2float(s_p[CLAMP(d4.x)]);
        r.y = __low2float(s_p[CLAMP(s4.y)]) + __high2float(s_p[CLAMP(d4.y)]);
        r.z = __low2float(s_p[CLAMP(s4.z)]) + __high2float(s_p[CLAMP(d4.z)]);
        r.w = __low2float(s_p[CLAMP(s4.w)]) + __high2float(s_p[CLAMP(d4.w)]);
        *reinterpret_cast<float4*>(out + q * 4) = r;
    }
    if (blockIdx.x == 0) {
        for (int e = total_quads * 4 + tid; e < n_edges; e += blockDim.x) {
            int s = CLAMP(ei[e]);
            int d = CLAMP(ei[n_edges + e]);
            out[e] = __low2float(s_p[s]) + __high2float(s_p[d]);
        }
    }
}

extern "C" void kernel_launch(void* const* d_in, const int* in_sizes, int n_in,
                              void* d_out, int out_size) {
    const float* X  = (const float*)d_in[0];
    const int*   ei = (const int*)d_in[1];     // [2, E] int32
    const float* W1 = (const float*)d_in[2];
    const float* W2 = (const float*)d_in[3];
    float* out = (float*)d_out;

    int n_nodes = in_sizes[0] / D;             // 50000
    int n_edges = in_sizes[1] / 2;             // 640000

    static int n_sms = 0;
    if (n_sms == 0) {
        cudaDeviceGetAttribute(&n_sms, cudaDevAttrMultiProcessorCount, 0);
        if (n_sms <= 0) n_sms = 148;
        cudaFuncSetAttribute(fused_kernel,
                             cudaFuncAttributeMaxDynamicSharedMemorySize,
                             SMEM_TOTAL);
    }

    // One block per SM; co-residency guaranteed (200KB smem => 1 block/SM,
    // grid == SM count), so the grid-wide spin cannot deadlock.
    fused_kernel<<<n_sms, 1024, SMEM_TOTAL>>>(X, ei, W1, W2, out,
                                              n_nodes, n_edges);
}